// round 1
// baseline (speedup 1.0000x reference)
#include <cuda_runtime.h>
#include <cstdint>

#define M_TOTAL 32768      // B*N = 8*4096
#define D_EMB   768
#define VOCAB   4096
#define HID     128
#define KH      256        // concat hidden (spatial 128 + feature 128)

#define BM 128
#define BN 128
#define BK 16

// Scratch (no cudaMalloc allowed)
__device__ float g_H[M_TOTAL * KH];        // hidden activations [M, 256]
__device__ float g_X[(size_t)M_TOTAL * D_EMB];  // combined embedding [M, 768]
__device__ float g_csq[VOCAB];             // ||c||^2

typedef unsigned long long u64;

__device__ __forceinline__ u64 pack2(float x, float y) {
    u64 r;
    unsigned xi = __float_as_uint(x), yi = __float_as_uint(y);
    asm("mov.b64 %0, {%1, %2};" : "=l"(r) : "r"(xi), "r"(yi));
    return r;
}
__device__ __forceinline__ void unpack2(u64 v, float& x, float& y) {
    unsigned xi, yi;
    asm("mov.b64 {%0, %1}, %2;" : "=r"(xi), "=r"(yi) : "l"(v));
    x = __uint_as_float(xi); y = __uint_as_float(yi);
}
__device__ __forceinline__ u64 fma2(u64 a, u64 b, u64 c) {
    u64 d;
    asm("fma.rn.f32x2 %0, %1, %2, %3;" : "=l"(d) : "l"(a), "l"(b), "l"(c));
    return d;
}

// ---------------------------------------------------------------------------
// Kernel 1: hidden activations H[m, 0:128] = relu(coords@Ws1+bs1),
//                              H[m, 128:256] = relu(feats@Wf1+bf1)
// ---------------------------------------------------------------------------
__global__ void hidden_kernel(const float* __restrict__ coords,
                              const float* __restrict__ feats,
                              const float* __restrict__ Ws1, const float* __restrict__ bs1,
                              const float* __restrict__ Wf1, const float* __restrict__ bf1) {
    int t = blockIdx.x * blockDim.x + threadIdx.x;   // [0, M*256)
    int m = t >> 8;
    int j = t & 255;
    float acc;
    if (j < HID) {
        float c0 = coords[m * 2 + 0];
        float c1 = coords[m * 2 + 1];
        acc = bs1[j] + c0 * Ws1[j] + c1 * Ws1[HID + j];
    } else {
        int jj = j - HID;
        acc = bf1[jj];
#pragma unroll
        for (int i = 0; i < 10; i++)
            acc += feats[m * 10 + i] * Wf1[i * HID + jj];
    }
    g_H[t] = fmaxf(acc, 0.0f);
}

// ---------------------------------------------------------------------------
// Kernel 2: per-codeword squared norms
// ---------------------------------------------------------------------------
__global__ void csq_kernel(const float* __restrict__ cb) {
    int w = (blockIdx.x * blockDim.x + threadIdx.x) >> 5;
    int lane = threadIdx.x & 31;
    if (w >= VOCAB) return;
    const float* row = cb + (size_t)w * D_EMB;
    float s = 0.f;
    for (int i = lane; i < D_EMB; i += 32) { float v = row[i]; s += v * v; }
#pragma unroll
    for (int o = 16; o; o >>= 1) s += __shfl_down_sync(0xffffffffu, s, o);
    if (lane == 0) g_csq[w] = s;
}

// ---------------------------------------------------------------------------
// Kernel 3: X = H[32768,256] @ W2cat[256,768] + (bs2+bf2)
// W2cat rows 0..127 = Ws2, rows 128..255 = Wf2. f32x2-packed SGEMM.
// ---------------------------------------------------------------------------
__global__ __launch_bounds__(256) void embed_gemm_kernel(
    const float* __restrict__ Ws2, const float* __restrict__ bs2,
    const float* __restrict__ Wf2, const float* __restrict__ bf2) {
    __shared__ float As[BK][BM];
    __shared__ float Bs[BK][BN];
    int tid = threadIdx.x;
    int tx = tid & 15, ty = tid >> 4;
    int m0 = blockIdx.x * BM;
    int n0 = blockIdx.y * BN;

    u64 acc[8][4];
#pragma unroll
    for (int i = 0; i < 8; i++)
#pragma unroll
        for (int j = 0; j < 4; j++) acc[i][j] = 0ull;

    for (int kt = 0; kt < KH / BK; kt++) {
        // A tile: g_H[m0+m][kt*16 + k] -> As[k][m]  (transposed store)
#pragma unroll
        for (int e = 0; e < 2; e++) {
            int s = tid * 2 + e;              // 0..511
            int m = s >> 2, kq = s & 3;
            float4 v = *(const float4*)(g_H + (size_t)(m0 + m) * KH + kt * BK + kq * 4);
            As[kq * 4 + 0][m] = v.x; As[kq * 4 + 1][m] = v.y;
            As[kq * 4 + 2][m] = v.z; As[kq * 4 + 3][m] = v.w;
        }
        // B tile: W2cat[kg][n0+n] -> Bs[k][n]  (direct)
#pragma unroll
        for (int e = 0; e < 2; e++) {
            int s = tid * 2 + e;
            int k = s >> 5;
            int n = (s & 31) * 4;
            int kg = kt * BK + k;
            const float* src = (kg < HID) ? (Ws2 + (size_t)kg * D_EMB)
                                          : (Wf2 + (size_t)(kg - HID) * D_EMB);
            *(float4*)&Bs[k][n] = *(const float4*)(src + n0 + n);
        }
        __syncthreads();
#pragma unroll
        for (int k = 0; k < BK; k++) {
            ulonglong2 p0 = *(const ulonglong2*)&Bs[k][tx * 8];
            ulonglong2 p1 = *(const ulonglong2*)&Bs[k][tx * 8 + 4];
            u64 b[4] = {p0.x, p0.y, p1.x, p1.y};
            float4 a0 = *(const float4*)&As[k][ty * 8];
            float4 a1 = *(const float4*)&As[k][ty * 8 + 4];
            u64 ad[8];
            ad[0] = pack2(a0.x, a0.x); ad[1] = pack2(a0.y, a0.y);
            ad[2] = pack2(a0.z, a0.z); ad[3] = pack2(a0.w, a0.w);
            ad[4] = pack2(a1.x, a1.x); ad[5] = pack2(a1.y, a1.y);
            ad[6] = pack2(a1.z, a1.z); ad[7] = pack2(a1.w, a1.w);
#pragma unroll
            for (int i = 0; i < 8; i++)
#pragma unroll
                for (int j = 0; j < 4; j++)
                    acc[i][j] = fma2(ad[i], b[j], acc[i][j]);
        }
        __syncthreads();
    }
    // epilogue: add summed biases, store to g_X
#pragma unroll
    for (int j = 0; j < 4; j++) {
        int c = n0 + tx * 8 + j * 2;
        float bb0 = bs2[c] + bf2[c];
        float bb1 = bs2[c + 1] + bf2[c + 1];
#pragma unroll
        for (int i = 0; i < 8; i++) {
            float lo, hi; unpack2(acc[i][j], lo, hi);
            float2 o = make_float2(lo + bb0, hi + bb1);
            *(float2*)(g_X + (size_t)(m0 + ty * 8 + i) * D_EMB + c) = o;
        }
    }
}

// ---------------------------------------------------------------------------
// Kernel 4: VQ. For each row of X: argmin_v ( ||c_v||^2 - 2 x.c_v ),
// fused argmin + codebook gather. Each block owns 128 rows x full vocab.
// ---------------------------------------------------------------------------
__global__ __launch_bounds__(256) void vq_kernel(const float* __restrict__ cb,
                                                 float* __restrict__ out_tok,
                                                 float* __restrict__ out_q) {
    __shared__ float As[BK][BM];
    __shared__ float Bs[BK][BN];
    __shared__ float s_val[BM][17];
    __shared__ int   s_idx[BM][17];
    __shared__ int   s_tok[BM];
    int tid = threadIdx.x;
    int tx = tid & 15, ty = tid >> 4;
    int m0 = blockIdx.x * BM;

    float bv[8]; int bi[8];
#pragma unroll
    for (int i = 0; i < 8; i++) { bv[i] = 3.4e38f; bi[i] = 0; }

    for (int vt = 0; vt < VOCAB / BN; vt++) {
        int v0 = vt * BN;
        u64 acc[8][4];
#pragma unroll
        for (int i = 0; i < 8; i++)
#pragma unroll
            for (int j = 0; j < 4; j++) acc[i][j] = 0ull;

        for (int kt = 0; kt < D_EMB / BK; kt++) {
            // A tile: g_X rows (transposed into As)
#pragma unroll
            for (int e = 0; e < 2; e++) {
                int s = tid * 2 + e;
                int m = s >> 2, kq = s & 3;
                float4 v = *(const float4*)(g_X + (size_t)(m0 + m) * D_EMB + kt * BK + kq * 4);
                As[kq * 4 + 0][m] = v.x; As[kq * 4 + 1][m] = v.y;
                As[kq * 4 + 2][m] = v.z; As[kq * 4 + 3][m] = v.w;
            }
            // B tile: codebook rows (transposed into Bs)
#pragma unroll
            for (int e = 0; e < 2; e++) {
                int s = tid * 2 + e;
                int vv = s >> 2, kq = s & 3;
                float4 v = *(const float4*)(cb + (size_t)(v0 + vv) * D_EMB + kt * BK + kq * 4);
                Bs[kq * 4 + 0][vv] = v.x; Bs[kq * 4 + 1][vv] = v.y;
                Bs[kq * 4 + 2][vv] = v.z; Bs[kq * 4 + 3][vv] = v.w;
            }
            __syncthreads();
#pragma unroll
            for (int k = 0; k < BK; k++) {
                ulonglong2 p0 = *(const ulonglong2*)&Bs[k][tx * 8];
                ulonglong2 p1 = *(const ulonglong2*)&Bs[k][tx * 8 + 4];
                u64 b[4] = {p0.x, p0.y, p1.x, p1.y};
                float4 a0 = *(const float4*)&As[k][ty * 8];
                float4 a1 = *(const float4*)&As[k][ty * 8 + 4];
                u64 ad[8];
                ad[0] = pack2(a0.x, a0.x); ad[1] = pack2(a0.y, a0.y);
                ad[2] = pack2(a0.z, a0.z); ad[3] = pack2(a0.w, a0.w);
                ad[4] = pack2(a1.x, a1.x); ad[5] = pack2(a1.y, a1.y);
                ad[6] = pack2(a1.z, a1.z); ad[7] = pack2(a1.w, a1.w);
#pragma unroll
                for (int i = 0; i < 8; i++)
#pragma unroll
                    for (int j = 0; j < 4; j++)
                        acc[i][j] = fma2(ad[i], b[j], acc[i][j]);
            }
            __syncthreads();
        }
        // epilogue for this vocab tile: dist = csq[v] - 2*dot, track argmin
#pragma unroll
        for (int j = 0; j < 4; j++) {
            int v = v0 + tx * 8 + j * 2;
            float c0 = g_csq[v], c1 = g_csq[v + 1];
#pragma unroll
            for (int i = 0; i < 8; i++) {
                float lo, hi; unpack2(acc[i][j], lo, hi);
                float d0 = fmaf(-2.0f, lo, c0);
                float d1 = fmaf(-2.0f, hi, c1);
                if (d0 < bv[i]) { bv[i] = d0; bi[i] = v; }
                if (d1 < bv[i]) { bv[i] = d1; bi[i] = v + 1; }
            }
        }
    }

    // cross-thread argmin per row (16 column-group candidates per row)
#pragma unroll
    for (int i = 0; i < 8; i++) {
        s_val[ty * 8 + i][tx] = bv[i];
        s_idx[ty * 8 + i][tx] = bi[i];
    }
    __syncthreads();
    if (tid < BM) {
        float best = s_val[tid][0]; int bidx = s_idx[tid][0];
#pragma unroll
        for (int j = 1; j < 16; j++) {
            float v = s_val[tid][j];
            int   ix = s_idx[tid][j];
            if (v < best || (v == best && ix < bidx)) { best = v; bidx = ix; }
        }
        out_tok[m0 + tid] = (float)bidx;
        s_tok[tid] = bidx;
    }
    __syncthreads();
    // gather quantized rows from codebook (L2-hot)
    for (int s2 = tid; s2 < BM * (D_EMB / 4); s2 += 256) {
        int r = s2 / (D_EMB / 4);
        int c = (s2 % (D_EMB / 4)) * 4;
        float4 v = *(const float4*)(cb + (size_t)s_tok[r] * D_EMB + c);
        *(float4*)(out_q + (size_t)(m0 + r) * D_EMB + c) = v;
    }
}

// ---------------------------------------------------------------------------
extern "C" void kernel_launch(void* const* d_in, const int* in_sizes, int n_in,
                              void* d_out, int out_size) {
    const float* coords = (const float*)d_in[0];
    const float* feats  = (const float*)d_in[1];
    const float* Ws1 = (const float*)d_in[2];
    const float* bs1 = (const float*)d_in[3];
    const float* Ws2 = (const float*)d_in[4];
    const float* bs2 = (const float*)d_in[5];
    const float* Wf1 = (const float*)d_in[6];
    const float* bf1 = (const float*)d_in[7];
    const float* Wf2 = (const float*)d_in[8];
    const float* bf2 = (const float*)d_in[9];
    const float* cb  = (const float*)d_in[10];

    float* outf    = (float*)d_out;
    float* out_tok = outf;                 // tokens [32768] as float
    float* out_q   = outf + M_TOTAL;       // quantized [32768, 768]

    hidden_kernel<<<M_TOTAL, 256>>>(coords, feats, Ws1, bs1, Wf1, bf1);
    csq_kernel<<<VOCAB / 8, 256>>>(cb);
    dim3 g2(M_TOTAL / BM, D_EMB / BN);
    embed_gemm_kernel<<<g2, 256>>>(Ws2, bs2, Wf2, bf2);
    vq_kernel<<<M_TOTAL / BM, 256>>>(cb, out_tok, out_q);
}